// round 13
// baseline (speedup 1.0000x reference)
#include <cuda_runtime.h>

// TritonDualLIF: x [T=16,B=32,N=196,C=512] f32, decay scalar.
// v = d*v + x[t]; vpool[t,b,c] = mean_n(pre-reset v); s = (v>=1); v = s?0:v.
// out = spikes [T,B,N,C] ++ vpool [T,B,C].
//
// Persistent balanced grid: 512 CTAs (single resident wave), each processes
// exactly 2 of the 1024 (cblk,b,z) work items. Body = R9 champion loop
// (float2, NH=4 chunks of 49, t+1 register prefetch). Mod-4 last-arrival
// election combines chunk partials into vpool.

#define T_ 16
#define B_ 32
#define N_ 196
#define C_ 512
#define C2 (C_ / 2)        // 256 float2 per row
#define NH 4
#define NSUB 49
#define NLANES 8
#define JMAX 7             // ty==0 -> 7 rows, else 6
#define NGROUP 256         // B_ * (C2/32)
#define NCTA 512           // persistent CTAs; 2 items each
#define NITEM 1024

// Per-chunk partial sums: [NH][group][T*32] float2 = 4 MB.
__device__ float2   g_part[NH * NGROUP * T_ * 32];
__device__ unsigned g_ctr[NGROUP];   // parity mod 4 elects the combiner

__global__ __launch_bounds__(256, 4)
void lif_dual_kernel(const float2* __restrict__ x,
                     const float* __restrict__ decay,
                     float* __restrict__ out) {
    const int tx  = threadIdx.x;      // c2 lane 0..31
    const int ty  = threadIdx.y;      // n lane 0..7
    const int tid = ty * 32 + tx;
    const float d = decay[0];

    float2* __restrict__ spikes = (float2*)out;
    float2* __restrict__ vpool  = (float2*)(out + (size_t)T_ * B_ * N_ * C_);

    __shared__ float2 red[NLANES][T_][32];  // exclusive slots, no in-loop sync
    __shared__ int    s_last;

    const unsigned tstride = (unsigned)(B_ * N_ * C2);
    const int jcnt = (ty == 0) ? JMAX : (JMAX - 1);

#pragma unroll 1
    for (int it = 0; it < 2; ++it) {
        const int item = (int)blockIdx.x + it * NCTA;   // 0..1023
        const int z    = item >> 8;                     // 0..3
        const int rem  = item & 255;
        const int b    = rem >> 3;                      // 0..31
        const int cblk = rem & 7;                       // 0..7

        const unsigned c2    = (unsigned)cblk * 32u + (unsigned)tx;
        const unsigned bbase = (unsigned)b * (N_ * C2)
                             + (unsigned)(z * NSUB + ty) * C2 + c2;

        float2 v[JMAX];
        float2 xc[JMAX];
#pragma unroll
        for (int j = 0; j < JMAX; ++j) v[j] = make_float2(0.f, 0.f);

        // Prologue: load t=0 inputs.
#pragma unroll
        for (int j = 0; j < JMAX; ++j)
            if (j < jcnt) xc[j] = x[bbase + (unsigned)(j * (NLANES * C2))];

        for (int t = 0; t < T_; ++t) {
            const unsigned tb = (unsigned)t * tstride + bbase;

            // Prefetch t+1 BEFORE consuming t (keeps ~12 loads in flight).
            float2 xn[JMAX];
            if (t + 1 < T_) {
                const unsigned nb = tb + tstride;
#pragma unroll
                for (int j = 0; j < JMAX; ++j)
                    if (j < jcnt) xn[j] = x[nb + (unsigned)(j * (NLANES * C2))];
            }

            float2 part = make_float2(0.f, 0.f);
#pragma unroll
            for (int j = 0; j < JMAX; ++j) {
                if (j < jcnt) {
                    const unsigned idx = tb + (unsigned)(j * (NLANES * C2));
                    float2 vv;
                    vv.x = fmaf(d, v[j].x, xc[j].x);
                    vv.y = fmaf(d, v[j].y, xc[j].y);
                    part.x += vv.x;                   // pre-reset membrane
                    part.y += vv.y;
                    const bool fx = (vv.x >= 1.0f);
                    const bool fy = (vv.y >= 1.0f);
                    float2 s;
                    s.x = fx ? 1.0f : 0.0f;
                    s.y = fy ? 1.0f : 0.0f;
                    spikes[idx] = s;
                    v[j].x = fx ? 0.0f : vv.x;        // hard reset
                    v[j].y = fy ? 0.0f : vv.y;
                }
            }
            red[ty][t][tx] = part;                    // exclusive slot

#pragma unroll
            for (int j = 0; j < JMAX; ++j) xc[j] = xn[j];
        }

        __syncthreads();

        // Reduce 8 lanes -> chunk partial [T_*32] float2, store to scratch.
        const int group = b * 8 + cblk;               // 0..255
        float2* gp = &g_part[((unsigned)z * NGROUP + (unsigned)group) * (T_ * 32)];
#pragma unroll
        for (int o = 0; o < 2; ++o) {
            const int oi = tid + o * 256;             // 0..511
            const int t  = oi >> 5;
            const int cc = oi & 31;
            float2 sum = red[0][t][cc];
#pragma unroll
            for (int k = 1; k < NLANES; ++k) {
                sum.x += red[k][t][cc].x;
                sum.y += red[k][t][cc].y;
            }
            gp[oi] = sum;
        }

        __threadfence();
        __syncthreads();
        if (tid == 0) {
            const unsigned old = atomicAdd(&g_ctr[group], 1u);
            s_last = ((old & 3u) == 3u) ? 1 : 0;
        }
        __syncthreads();

        if (s_last) {
            __threadfence();   // acquire: see all chunks' scratch writes
            const float2* p0 = &g_part[((unsigned)group) * (T_ * 32)];
            const float2* p1 = &g_part[((unsigned)(NGROUP + group)) * (T_ * 32)];
            const float2* p2 = &g_part[((unsigned)(2 * NGROUP + group)) * (T_ * 32)];
            const float2* p3 = &g_part[((unsigned)(3 * NGROUP + group)) * (T_ * 32)];
#pragma unroll
            for (int o = 0; o < 2; ++o) {
                const int oi = tid + o * 256;
                const int t  = oi >> 5;
                const int cc = oi & 31;
                float2 r;
                r.x = ((p0[oi].x + p1[oi].x) + (p2[oi].x + p3[oi].x)) * (1.0f / (float)N_);
                r.y = ((p0[oi].y + p1[oi].y) + (p2[oi].y + p3[oi].y)) * (1.0f / (float)N_);
                vpool[(unsigned)t * (B_ * C2) + (unsigned)b * C2
                      + (unsigned)cblk * 32u + (unsigned)cc] = r;
            }
        }
        __syncthreads();   // protect red[] / s_last before next item
    }
}

extern "C" void kernel_launch(void* const* d_in, const int* in_sizes, int n_in,
                              void* d_out, int out_size) {
    const float2* x    = (const float2*)d_in[0];
    const float* decay = (const float*)d_in[1];
    float* out = (float*)d_out;

    dim3 block(32, NLANES);             // 256 threads
    dim3 grid(NCTA);                    // 512 persistent CTAs, single wave
    lif_dual_kernel<<<grid, block>>>(x, decay, out);
}

// round 14
// speedup vs baseline: 1.0381x; 1.0381x over previous
#include <cuda_runtime.h>

// TritonDualLIF: x [T=16,B=32,N=196,C=512] f32, decay scalar.
// v = d*v + x[t]; vpool[t,b,c] = mean_n(pre-reset v); s = (v>=1); v = s?0:v.
// out = spikes [T,B,N,C] ++ vpool [T,B,C].
//
// Full-row layout: each CTA owns all C (256 float2 lanes) x 7 CONSECUTIVE
// n-rows -> one dense 14KB read extent + one dense 14KB write extent per
// (CTA, timestep). No smem, no barriers, no scratch: the N-mean is a
// within-thread partial accumulated into vpool with atomicAdd (28 adds per
// output, fp-order error ~1e-7). vpool is zeroed via cudaMemsetAsync.

#define T_ 16
#define B_ 32
#define N_ 196
#define C_ 512
#define C2 (C_ / 2)        // 256 float2 per row
#define NH 28              // chunks of 7 consecutive rows (28*7 = 196)
#define ROWS 7

__global__ __launch_bounds__(256, 4)
void lif_dual_kernel(const float2* __restrict__ x,
                     const float* __restrict__ decay,
                     float* __restrict__ out) {
    const int tid = threadIdx.x;      // c2 lane 0..255 (full C coverage)
    const int b   = blockIdx.x;       // 0..31
    const int z   = blockIdx.y;       // 0..27 (7-row chunk)
    const float d = decay[0];

    float2* __restrict__ spikes = (float2*)out;
    float*  __restrict__ vpool  = out + (size_t)T_ * B_ * N_ * C_;

    float2 v[ROWS];
    float2 xc[ROWS];
#pragma unroll
    for (int j = 0; j < ROWS; ++j) v[j] = make_float2(0.f, 0.f);

    const unsigned bbase   = (unsigned)b * (N_ * C2)
                           + (unsigned)(z * ROWS) * C2 + (unsigned)tid;
    const unsigned tstride = (unsigned)(B_ * N_ * C2);

    // vpool address for this (b, c2) pair; +t*B_*C2 per timestep.
    float* vp = vpool + (unsigned)b * C_ + (unsigned)tid * 2u;
    const float inv = 1.0f / (float)N_;

    // Prologue: load t=0 inputs (7 consecutive rows = dense 14KB per CTA).
#pragma unroll
    for (int j = 0; j < ROWS; ++j)
        xc[j] = x[bbase + (unsigned)(j * C2)];

    for (int t = 0; t < T_; ++t) {
        const unsigned tb = (unsigned)t * tstride + bbase;

        // Prefetch t+1 before consuming t (keeps ~14 loads in flight).
        float2 xn[ROWS];
        if (t + 1 < T_) {
            const unsigned nb = tb + tstride;
#pragma unroll
            for (int j = 0; j < ROWS; ++j)
                xn[j] = x[nb + (unsigned)(j * C2)];
        }

        float2 part = make_float2(0.f, 0.f);
#pragma unroll
        for (int j = 0; j < ROWS; ++j) {
            const unsigned idx = tb + (unsigned)(j * C2);
            float2 vv;
            vv.x = fmaf(d, v[j].x, xc[j].x);
            vv.y = fmaf(d, v[j].y, xc[j].y);
            part.x += vv.x;                   // pre-reset membrane
            part.y += vv.y;
            const bool fx = (vv.x >= 1.0f);
            const bool fy = (vv.y >= 1.0f);
            float2 s;
            s.x = fx ? 1.0f : 0.0f;
            s.y = fy ? 1.0f : 0.0f;
            spikes[idx] = s;
            v[j].x = fx ? 0.0f : vv.x;        // hard reset
            v[j].y = fy ? 0.0f : vv.y;
        }

        // Accumulate this chunk's 7-row partial into vpool (28 adds/output).
        float* vpt = vp + (unsigned)t * (B_ * C_);
        atomicAdd(vpt,     part.x * inv);
        atomicAdd(vpt + 1, part.y * inv);

#pragma unroll
        for (int j = 0; j < ROWS; ++j) xc[j] = xn[j];
    }
}

extern "C" void kernel_launch(void* const* d_in, const int* in_sizes, int n_in,
                              void* d_out, int out_size) {
    const float2* x    = (const float2*)d_in[0];
    const float* decay = (const float*)d_in[1];
    float* out = (float*)d_out;

    // Zero the vpool region (accumulated atomically by the kernel).
    float* vpool = out + (size_t)T_ * B_ * N_ * C_;
    cudaMemsetAsync(vpool, 0, (size_t)T_ * B_ * C_ * sizeof(float));

    dim3 block(256);
    dim3 grid(B_, NH);                  // 32 x 28 = 896 CTAs
    lif_dual_kernel<<<grid, block>>>(x, decay, out);
}